// round 14
// baseline (speedup 1.0000x reference)
#include <cuda_runtime.h>
#include <cuda_bf16.h>
#include <math.h>
#include <stdint.h>

// ---------------- problem constants ----------------
#define DD 16
#define HH 256
#define MM 3
#define NN 65536

// ---------------- table config ----------------
#define T_TAB 142
#define NPTS  144              // 142 grid + x=-1 + x=+1; 9 M-tiles of 16
#define MTILE 16
#define BPN   9                // blocks per net -> 144 CTAs, one wave
#define XMN   (-6.0f)
#define DXI   (12.0f / 141.0f)
#define INV_DX (141.0f / 12.0f)

// A smem pitch (bf16 elems): multiple of 8 (16B rows for ldmatrix),
// 560B rows -> ldmatrix row phases conflict-free.
#define APITCH 280
#define ABUFB  (MTILE * APITCH * 2)    // bytes per A buffer (8960)

// W_mid is [l][d][256][256]: next LAYER (same net) is +DD*65536 floats.
#define WL_NEXT (DD * 65536)

// ---------------- device scratch ----------------
__device__ float g_table[DD][T_TAB];
__device__ float g_ymm[DD][2];

// ==================== helpers ====================
__device__ __forceinline__ uint32_t smem_to_u32(const void* smem_ptr) {
    uint32_t addr;
    asm("{ .reg .u64 tmp; cvta.to.shared.u64 tmp, %1; cvt.u32.u64 %0, tmp; }"
        : "=r"(addr) : "l"(smem_ptr));
    return addr;
}

// exact tanh identity via fast MUFU ex2/rcp: ~1e-7 abs err, saturates correctly
__device__ __forceinline__ float tanh_fast(float x) {
    float e = __expf(2.0f * x);
    return 1.0f - __fdividef(2.0f, e + 1.0f);
}

// (a,b) fp32 -> packed bf16x2 hi + bf16x2 lo (residual); lo16 = a, hi16 = b
__device__ __forceinline__ void split2(float a, float b, unsigned& hi, unsigned& lo) {
    __nv_bfloat16 ha = __float2bfloat16(a), hb = __float2bfloat16(b);
    __nv_bfloat16 la = __float2bfloat16(a - __bfloat162float(ha));
    __nv_bfloat16 lb = __float2bfloat16(b - __bfloat162float(hb));
    hi = (unsigned)__bfloat16_as_ushort(ha) | ((unsigned)__bfloat16_as_ushort(hb) << 16);
    lo = (unsigned)__bfloat16_as_ushort(la) | ((unsigned)__bfloat16_as_ushort(lb) << 16);
}

#define MMA_BF16(d, a, b0, b1) \
    asm volatile("mma.sync.aligned.m16n8k16.row.col.f32.bf16.bf16.f32 " \
        "{%0,%1,%2,%3}, {%4,%5,%6,%7}, {%8,%9}, {%0,%1,%2,%3};" \
        : "+f"((d)[0]), "+f"((d)[1]), "+f"((d)[2]), "+f"((d)[3]) \
        : "r"((a)[0]), "r"((a)[1]), "r"((a)[2]), "r"((a)[3]), "r"(b0), "r"(b1))

#define LDMATRIX_X4(r, addr) \
    asm volatile("ldmatrix.sync.aligned.m8n8.x4.shared.b16 {%0,%1,%2,%3}, [%4];" \
        : "=r"((r)[0]), "=r"((r)[1]), "=r"((r)[2]), "=r"((r)[3]) : "r"(addr))

// load one B fragment's 4 fp32 source values: W[k0][n], W[k0+1][n],
// W[k0+8][n], W[k0+9][n]  (row-major [k][256], p = &W[k0*256 + n])
__device__ __forceinline__ void loadB4(const float* __restrict__ p, float w[4]) {
    w[0] = __ldg(p);
    w[1] = __ldg(p + 256);
    w[2] = __ldg(p + 2048);
    w[3] = __ldg(p + 2304);
}

// ---------------------------------------------------------------------------
// Build (fused weight conversion): per (net, point-tile of 16) CTA,
// 512 threads (16 warps). Warp w owns output columns [16w, 16w+16).
// B fragments are built inline from fp32 W_mid (4 scalar LDG + split2);
// 3-term split with 3 INDEPENDENT accumulator sets (no per-kt RAW chain).
// Double-buffered A (one sync/layer) + 1-kt-ahead weight prefetch.
// ---------------------------------------------------------------------------
__global__ __launch_bounds__(512) void build_kernel(
    const float* __restrict__ W_in,  const float* __restrict__ b_in,
    const float* __restrict__ W_mid, const float* __restrict__ b_mid,
    const float* __restrict__ W_out, const float* __restrict__ b_out)
{
    __shared__ __align__(16) unsigned short A_hi[2][MTILE][APITCH];
    __shared__ __align__(16) unsigned short A_lo[2][MTILE][APITCH];
    __shared__ float red[16][MTILE];

    const int t    = threadIdx.x;
    const int wid  = t >> 5;
    const int lane = t & 31;
    const int tq   = lane & 3;
    const int g    = lane >> 2;
    const int d    = blockIdx.x / BPN;
    const int blk  = blockIdx.x % BPN;

    // per-lane W offsets: addr(kt,nt) = Wl + kt*4096 + tq*512 + n_nt
    const int lo0 = tq * 512 + (wid * 2 + 0) * 8 + g;
    const int lo1 = tq * 512 + (wid * 2 + 1) * 8 + g;

    // hoist (l=0, kt=0) weight loads above the input layer (hide latency)
    const float* W0 = W_mid + ((size_t)d << 16);
    float wc0[4], wc1[4];
    loadB4(W0 + lo0, wc0);
    loadB4(W0 + lo1, wc1);

    // ---- input layer: A0[m][k] = tanh(W_in[k]*x_m + b_in[k]) -> buffer 0 ----
    {
        const int m  = t & 15;
        const int kc = t >> 4;        // k chunk of 8
        const int pidx = blk * MTILE + m;
        float xp;
        if (pidx < T_TAB)       xp = XMN + (float)pidx * DXI;
        else if (pidx == T_TAB) xp = -1.0f;
        else                    xp =  1.0f;
        const float* wi = W_in + d * HH;
        const float* bi = b_in + d * HH;
        #pragma unroll
        for (int kk = 0; kk < 8; kk += 2) {
            const int k = kc * 8 + kk;
            const float v0 = tanh_fast(fmaf(__ldg(&wi[k]),     xp, __ldg(&bi[k])));
            const float v1 = tanh_fast(fmaf(__ldg(&wi[k + 1]), xp, __ldg(&bi[k + 1])));
            unsigned hi, lo;
            split2(v0, v1, hi, lo);
            *(unsigned*)&A_hi[0][m][k] = hi;
            *(unsigned*)&A_lo[0][m][k] = lo;
        }
    }
    __syncthreads();

    const uint32_t Ahi_base = smem_to_u32(&A_hi[0][0][0]);
    const uint32_t Alo_base = smem_to_u32(&A_lo[0][0][0]);
    const uint32_t lm_off = (uint32_t)((lane & 15) * (APITCH * 2) + (lane >> 4) * 16);

    for (int l = 0; l < MM; ++l) {
        const int rb = l & 1;
        const int wb = rb ^ 1;
        const float* Wl = W_mid + ((size_t)(l * DD + d) << 16);
        const uint32_t rboff = (uint32_t)(rb * ABUFB);

        // three independent accumulator sets: main, A-residual, B-residual
        float accM[2][4], accC[2][4], accD[2][4];
        #pragma unroll
        for (int nt = 0; nt < 2; ++nt)
            #pragma unroll
            for (int e = 0; e < 4; ++e) {
                accM[nt][e] = 0.0f; accC[nt][e] = 0.0f; accD[nt][e] = 0.0f;
            }

        #pragma unroll 4
        for (int kt = 0; kt < 16; ++kt) {
            unsigned ah[4], al[4];
            const uint32_t ka = (uint32_t)(kt * 32);
            LDMATRIX_X4(ah, Ahi_base + rboff + lm_off + ka);
            LDMATRIX_X4(al, Alo_base + rboff + lm_off + ka);

            // prefetch next k-tile's (or next LAYER's first) W values
            float wn0[4], wn1[4];
            if (kt < 15) {
                loadB4(Wl + (kt + 1) * 4096 + lo0, wn0);
                loadB4(Wl + (kt + 1) * 4096 + lo1, wn1);
            } else if (l < MM - 1) {
                loadB4(Wl + WL_NEXT + lo0, wn0);   // +DD*65536: next layer, same net
                loadB4(Wl + WL_NEXT + lo1, wn1);
            } else {
                #pragma unroll
                for (int e = 0; e < 4; ++e) { wn0[e] = wc0[e]; wn1[e] = wc1[e]; }
            }

            // inline conversion of current weights -> fragments
            unsigned b0h0, b0l0, b1h0, b1l0, b0h1, b0l1, b1h1, b1l1;
            split2(wc0[0], wc0[1], b0h0, b0l0);
            split2(wc0[2], wc0[3], b1h0, b1l0);
            split2(wc1[0], wc1[1], b0h1, b0l1);
            split2(wc1[2], wc1[3], b1h1, b1l1);

            MMA_BF16(accM[0], ah, b0h0, b1h0);   // Ahi * Bhi
            MMA_BF16(accM[1], ah, b0h1, b1h1);
            MMA_BF16(accC[0], al, b0h0, b1h0);   // Alo * Bhi
            MMA_BF16(accC[1], al, b0h1, b1h1);
            MMA_BF16(accD[0], ah, b0l0, b1l0);   // Ahi * Blo
            MMA_BF16(accD[1], ah, b0l1, b1l1);

            #pragma unroll
            for (int e = 0; e < 4; ++e) { wc0[e] = wn0[e]; wc1[e] = wn1[e]; }
        }

        // merged accumulators
        float acc[2][4];
        #pragma unroll
        for (int nt = 0; nt < 2; ++nt)
            #pragma unroll
            for (int e = 0; e < 4; ++e)
                acc[nt][e] = accM[nt][e] + accC[nt][e] + accD[nt][e];

        if (l < MM - 1) {
            // epilogue -> write buffer wb (readers of rb are unaffected)
            const float* bm = b_mid + (size_t)(l * DD + d) * HH + wid * 16;
            #pragma unroll
            for (int nt = 0; nt < 2; ++nt) {
                const int ne = nt * 8 + tq * 2;
                const float2 bb = *(const float2*)&bm[ne];
                const int ncol = wid * 16 + ne;
                unsigned hi, lo;
                split2(tanh_fast(acc[nt][0] + bb.x),
                       tanh_fast(acc[nt][1] + bb.y), hi, lo);
                *(unsigned*)&A_hi[wb][g][ncol] = hi;
                *(unsigned*)&A_lo[wb][g][ncol] = lo;
                split2(tanh_fast(acc[nt][2] + bb.x),
                       tanh_fast(acc[nt][3] + bb.y), hi, lo);
                *(unsigned*)&A_hi[wb][g + 8][ncol] = hi;
                *(unsigned*)&A_lo[wb][g + 8][ncol] = lo;
            }
            __syncthreads();   // wb visible before next layer reads it
        } else {
            // final: y[m] = sum_n W_out[n]*tanh(D+b) + b_out
            const float* bm = b_mid + (size_t)(l * DD + d) * HH + wid * 16;
            const float* wo = W_out + d * HH + wid * 16;
            float pm[2] = {0.0f, 0.0f};
            #pragma unroll
            for (int nt = 0; nt < 2; ++nt) {
                const int ne = nt * 8 + tq * 2;
                const float2 bb = *(const float2*)&bm[ne];
                const float2 ww = *(const float2*)&wo[ne];
                pm[0] = fmaf(tanh_fast(acc[nt][0] + bb.x), ww.x, pm[0]);
                pm[0] = fmaf(tanh_fast(acc[nt][1] + bb.y), ww.y, pm[0]);
                pm[1] = fmaf(tanh_fast(acc[nt][2] + bb.x), ww.x, pm[1]);
                pm[1] = fmaf(tanh_fast(acc[nt][3] + bb.y), ww.y, pm[1]);
            }
            #pragma unroll
            for (int h = 0; h < 2; ++h) {
                pm[h] += __shfl_xor_sync(0xffffffffu, pm[h], 1);
                pm[h] += __shfl_xor_sync(0xffffffffu, pm[h], 2);
            }
            if (tq == 0) {
                red[wid][g]     = pm[0];
                red[wid][g + 8] = pm[1];
            }
            __syncthreads();
            if (t < MTILE) {
                float y = __ldg(&b_out[d]);
                #pragma unroll
                for (int w = 0; w < 16; ++w) y += red[w][t];
                const int pidx = blk * MTILE + t;
                if (pidx < T_TAB) g_table[d][pidx] = y;
                else              g_ymm[d][pidx - T_TAB] = y;  // 0: x=-1, 1: x=+1
            }
        }
    }
}

// ---------------------------------------------------------------------------
// Interp: Catmull-Rom through a SMEM-resident table + min-max normalization.
// Each block covers 4096 contiguous elements (one net), 16 elems/thread.
// ---------------------------------------------------------------------------
__global__ __launch_bounds__(256) void interp_kernel(
    const float* __restrict__ x, float* __restrict__ out)
{
    __shared__ float stab[T_TAB];

    const int t   = threadIdx.x;
    const int d   = blockIdx.x >> 4;          // 16 blocks per net
    const int i16 = blockIdx.x * 256 + t;     // unit of 16 elems (4 float4)

    if (t < T_TAB) stab[t] = g_table[d][t];
    const float ymin = g_ymm[d][0];
    const float s    = 2.0f / (g_ymm[d][1] - ymin);
    __syncthreads();

    #pragma unroll
    for (int q = 0; q < 4; ++q) {
        const float4 xv = reinterpret_cast<const float4*>(x)[4 * i16 + q];
        const float xin[4] = {xv.x, xv.y, xv.z, xv.w};
        float r[4];
        #pragma unroll
        for (int c = 0; c < 4; ++c) {
            float u = (xin[c] - XMN) * INV_DX;
            u = fminf(fmaxf(u, 0.0f), 141.0f);
            int i = (int)floorf(u);
            i = min(max(i, 1), T_TAB - 3);
            const float tt = u - (float)i;
            const float p0 = stab[i - 1];
            const float p1 = stab[i];
            const float p2 = stab[i + 1];
            const float p3 = stab[i + 2];
            const float y = p1 + 0.5f * tt * ((p2 - p0)
                            + tt * ((2.0f * p0 - 5.0f * p1 + 4.0f * p2 - p3)
                            + tt * (3.0f * (p1 - p2) + p3 - p0)));
            r[c] = fmaf(y - ymin, s, -1.0f);
        }
        reinterpret_cast<float4*>(out)[4 * i16 + q] =
            make_float4(r[0], r[1], r[2], r[3]);
    }
}

// ---------------------------------------------------------------------------
extern "C" void kernel_launch(void* const* d_in, const int* in_sizes, int n_in,
                              void* d_out, int out_size)
{
    const float* x     = (const float*)d_in[0];
    const float* W_in  = (const float*)d_in[1];
    const float* b_in  = (const float*)d_in[2];
    const float* W_mid = (const float*)d_in[3];
    const float* b_mid = (const float*)d_in[4];
    const float* W_out = (const float*)d_in[5];
    const float* b_out = (const float*)d_in[6];

    build_kernel<<<DD * BPN, 512>>>(W_in, b_in, W_mid, b_mid, W_out, b_out);

    const int total16 = DD * NN / 16;
    interp_kernel<<<total16 / 256, 256>>>(x, (float*)d_out);
}

// round 15
// speedup vs baseline: 1.2289x; 1.2289x over previous
#include <cuda_runtime.h>
#include <cuda_bf16.h>
#include <math.h>
#include <stdint.h>

// ---------------- problem constants ----------------
#define DD 16
#define HH 256
#define MM 3
#define NN 65536

// ---------------- table config ----------------
#define T_TAB 142
#define NPTS  144              // 142 grid + x=-1 + x=+1; 9 M-tiles of 16
#define MTILE 16
#define BPN   9                // blocks per net -> 144 CTAs, one wave
#define XMN   (-6.0f)
#define DXI   (12.0f / 141.0f)
#define INV_DX (141.0f / 12.0f)

// A smem pitch (bf16 elems): multiple of 8 (16B rows for ldmatrix),
// 560B rows -> ldmatrix row phases conflict-free.
#define APITCH 280
#define ABUFB  (MTILE * APITCH * 2)    // bytes per A buffer (8960)

// prep SMEM pitch (fp32): gather banks (8tq + g + 8nt) mod 32: conflict-free.
#define PP2 132

// ---------------- device scratch ----------------
__device__ float g_table[DD][T_TAB];
__device__ float g_ymm[DD][2];
// staged weights in mma-fragment order:
// index (((l*DD+d)*16 + ktile)*32 + ntile)*32 + lane -> {b0h, b1h, b0l, b1l}
__device__ __align__(16) uint4 g_B[MM * DD * 16 * 32 * 32];
#define LSTRIDE (DD * 16 * 32 * 32)    // uint4 elems between layers (262144)

// ==================== helpers ====================
__device__ __forceinline__ uint32_t smem_to_u32(const void* smem_ptr) {
    uint32_t addr;
    asm("{ .reg .u64 tmp; cvta.to.shared.u64 tmp, %1; cvt.u32.u64 %0, tmp; }"
        : "=r"(addr) : "l"(smem_ptr));
    return addr;
}

// exact tanh identity via fast MUFU ex2/rcp: ~1e-7 abs err, saturates correctly
__device__ __forceinline__ float tanh_fast(float x) {
    float e = __expf(2.0f * x);
    return 1.0f - __fdividef(2.0f, e + 1.0f);
}

// (a,b) fp32 -> packed bf16x2 hi + bf16x2 lo (residual); lo16 = a, hi16 = b
__device__ __forceinline__ void split2(float a, float b, unsigned& hi, unsigned& lo) {
    __nv_bfloat16 ha = __float2bfloat16(a), hb = __float2bfloat16(b);
    __nv_bfloat16 la = __float2bfloat16(a - __bfloat162float(ha));
    __nv_bfloat16 lb = __float2bfloat16(b - __bfloat162float(hb));
    hi = (unsigned)__bfloat16_as_ushort(ha) | ((unsigned)__bfloat16_as_ushort(hb) << 16);
    lo = (unsigned)__bfloat16_as_ushort(la) | ((unsigned)__bfloat16_as_ushort(lb) << 16);
}

#define MMA_BF16(d, a, b0, b1) \
    asm volatile("mma.sync.aligned.m16n8k16.row.col.f32.bf16.bf16.f32 " \
        "{%0,%1,%2,%3}, {%4,%5,%6,%7}, {%8,%9}, {%0,%1,%2,%3};" \
        : "+f"((d)[0]), "+f"((d)[1]), "+f"((d)[2]), "+f"((d)[3]) \
        : "r"((a)[0]), "r"((a)[1]), "r"((a)[2]), "r"((a)[3]), "r"(b0), "r"(b1))

#define LDMATRIX_X4(r, addr) \
    asm volatile("ldmatrix.sync.aligned.m8n8.x4.shared.b16 {%0,%1,%2,%3}, [%4];" \
        : "=r"((r)[0]), "=r"((r)[1]), "=r"((r)[2]), "=r"((r)[3]) : "r"(addr))

// ---------------------------------------------------------------------------
// Prep: W_mid fp32 [l][d][k][n] -> g_B fragment-order bf16 hi/lo.
// Block = (nd, ktile, n-half): 1536 blocks x 128 threads, 8.4 KB smem.
// (Verbatim from the 27.6us R12 kernel — fusing this into build measured
//  ~2x slower due to scalar-LDG fragment gather; keep it staged.)
// ---------------------------------------------------------------------------
__global__ __launch_bounds__(128) void prep_kernel(const float* __restrict__ W_mid)
{
    __shared__ __align__(16) float s[16][PP2];
    const int bid = blockIdx.x;
    const int nh  = bid & 1;            // n half (128 cols)
    const int kt  = (bid >> 1) & 15;    // ktile
    const int nd  = bid >> 5;           // l*16 + d
    const int t   = threadIdx.x;

    // 16 rows x 128 floats, 4 x LDG.128 per thread
    {
        const int r = t >> 3;
        const int c = (t & 7) * 16;
        const float4* src = (const float4*)(W_mid + (size_t)nd * HH * HH
                                + (kt * 16 + r) * HH + nh * 128 + c);
        float4 v0 = __ldg(&src[0]); float4 v1 = __ldg(&src[1]);
        float4 v2 = __ldg(&src[2]); float4 v3 = __ldg(&src[3]);
        *(float4*)&s[r][c]      = v0; *(float4*)&s[r][c + 4]  = v1;
        *(float4*)&s[r][c + 8]  = v2; *(float4*)&s[r][c + 12] = v3;
    }
    __syncthreads();

    const int lane = t & 31;
    const int wid  = t >> 5;
    const int tq   = lane & 3;
    const int g    = lane >> 2;
    const int k0   = 2 * tq;
    uint4* out = g_B + ((size_t)nd * 16 + kt) * 32 * 32;
    #pragma unroll
    for (int it = 0; it < 4; ++it) {
        const int ntl = it * 4 + wid;       // local n-group within half
        const int n   = ntl * 8 + g;
        unsigned b0h, b0l, b1h, b1l;
        split2(s[k0][n],     s[k0 + 1][n], b0h, b0l);
        split2(s[k0 + 8][n], s[k0 + 9][n], b1h, b1l);
        out[(nh * 16 + ntl) * 32 + lane] = make_uint4(b0h, b1h, b0l, b1l);
    }
}

// ---------------------------------------------------------------------------
// Build: per (net, point-tile of 16) CTA, 512 threads (16 warps). Warp w owns
// output columns [16w, 16w+16). 3-term split: AhBh + AlBh + AhBl.
// Double-buffered A (one sync/layer) + cross-layer B prefetch. (Verbatim R12.)
// ---------------------------------------------------------------------------
__global__ __launch_bounds__(512) void build_kernel(
    const float* __restrict__ W_in,  const float* __restrict__ b_in,
    const float* __restrict__ b_mid,
    const float* __restrict__ W_out, const float* __restrict__ b_out)
{
    __shared__ __align__(16) unsigned short A_hi[2][MTILE][APITCH];
    __shared__ __align__(16) unsigned short A_lo[2][MTILE][APITCH];
    __shared__ float red[16][MTILE];

    const int t    = threadIdx.x;
    const int wid  = t >> 5;
    const int lane = t & 31;
    const int tq   = lane & 3;
    const int g    = lane >> 2;
    const int d    = blockIdx.x / BPN;
    const int blk  = blockIdx.x % BPN;

    // hoist layer-0 B fragment load above the input layer (hide latency)
    const uint4* __restrict__ Bw0 =
        g_B + ((size_t)d * 16 * 32 + wid * 2) * 32 + lane;
    uint4 Bc[2];
    Bc[0] = Bw0[0];
    Bc[1] = Bw0[32];

    // ---- input layer: A0[m][k] = tanh(W_in[k]*x_m + b_in[k]) -> buffer 0 ----
    {
        const int m  = t & 15;
        const int kc = t >> 4;        // k chunk of 8
        const int pidx = blk * MTILE + m;
        float xp;
        if (pidx < T_TAB)       xp = XMN + (float)pidx * DXI;
        else if (pidx == T_TAB) xp = -1.0f;
        else                    xp =  1.0f;
        const float* wi = W_in + d * HH;
        const float* bi = b_in + d * HH;
        #pragma unroll
        for (int kk = 0; kk < 8; kk += 2) {
            const int k = kc * 8 + kk;
            const float v0 = tanh_fast(fmaf(__ldg(&wi[k]),     xp, __ldg(&bi[k])));
            const float v1 = tanh_fast(fmaf(__ldg(&wi[k + 1]), xp, __ldg(&bi[k + 1])));
            unsigned hi, lo;
            split2(v0, v1, hi, lo);
            *(unsigned*)&A_hi[0][m][k] = hi;
            *(unsigned*)&A_lo[0][m][k] = lo;
        }
    }
    __syncthreads();

    const uint32_t Ahi_base = smem_to_u32(&A_hi[0][0][0]);
    const uint32_t Alo_base = smem_to_u32(&A_lo[0][0][0]);
    const uint32_t lm_off = (uint32_t)((lane & 15) * (APITCH * 2) + (lane >> 4) * 16);

    for (int l = 0; l < MM; ++l) {
        const int rb = l & 1;
        const int wb = rb ^ 1;
        const uint4* __restrict__ Bw =
            g_B + ((size_t)(l * DD + d) * 16 * 32 + wid * 2) * 32 + lane;
        const uint32_t rboff = (uint32_t)(rb * ABUFB);

        float acc[2][4];
        #pragma unroll
        for (int nt = 0; nt < 2; ++nt)
            #pragma unroll
            for (int e = 0; e < 4; ++e) acc[nt][e] = 0.0f;

        #pragma unroll 4
        for (int kt = 0; kt < 16; ++kt) {
            unsigned ah[4], al[4];
            const uint32_t ka = (uint32_t)(kt * 32);
            LDMATRIX_X4(ah, Ahi_base + rboff + lm_off + ka);
            LDMATRIX_X4(al, Alo_base + rboff + lm_off + ka);

            // prefetch: next k-tile, or next layer's first fragments
            uint4 Bn[2];
            if (kt < 15) {
                #pragma unroll
                for (int nt = 0; nt < 2; ++nt) Bn[nt] = Bw[(kt + 1) * 1024 + nt * 32];
            } else if (l < MM - 1) {
                #pragma unroll
                for (int nt = 0; nt < 2; ++nt) Bn[nt] = Bw[LSTRIDE + nt * 32];
            } else {
                #pragma unroll
                for (int nt = 0; nt < 2; ++nt) Bn[nt] = Bc[nt];
            }

            #pragma unroll
            for (int nt = 0; nt < 2; ++nt) {
                const unsigned b0h = Bc[nt].x, b1h = Bc[nt].y;
                const unsigned b0l = Bc[nt].z, b1l = Bc[nt].w;
                MMA_BF16(acc[nt], ah, b0h, b1h);   // Ahi * Bhi
                MMA_BF16(acc[nt], al, b0h, b1h);   // Alo * Bhi
                MMA_BF16(acc[nt], ah, b0l, b1l);   // Ahi * Blo
            }
            #pragma unroll
            for (int nt = 0; nt < 2; ++nt) Bc[nt] = Bn[nt];
        }

        if (l < MM - 1) {
            // epilogue -> write buffer wb (readers of rb are unaffected)
            const float* bm = b_mid + (size_t)(l * DD + d) * HH + wid * 16;
            #pragma unroll
            for (int nt = 0; nt < 2; ++nt) {
                const int ne = nt * 8 + tq * 2;
                const float2 bb = *(const float2*)&bm[ne];
                const int ncol = wid * 16 + ne;
                unsigned hi, lo;
                split2(tanh_fast(acc[nt][0] + bb.x),
                       tanh_fast(acc[nt][1] + bb.y), hi, lo);
                *(unsigned*)&A_hi[wb][g][ncol] = hi;
                *(unsigned*)&A_lo[wb][g][ncol] = lo;
                split2(tanh_fast(acc[nt][2] + bb.x),
                       tanh_fast(acc[nt][3] + bb.y), hi, lo);
                *(unsigned*)&A_hi[wb][g + 8][ncol] = hi;
                *(unsigned*)&A_lo[wb][g + 8][ncol] = lo;
            }
            __syncthreads();   // wb visible before next layer reads it
        } else {
            // final: y[m] = sum_n W_out[n]*tanh(D+b) + b_out
            const float* bm = b_mid + (size_t)(l * DD + d) * HH + wid * 16;
            const float* wo = W_out + d * HH + wid * 16;
            float pm[2] = {0.0f, 0.0f};
            #pragma unroll
            for (int nt = 0; nt < 2; ++nt) {
                const int ne = nt * 8 + tq * 2;
                const float2 bb = *(const float2*)&bm[ne];
                const float2 ww = *(const float2*)&wo[ne];
                pm[0] = fmaf(tanh_fast(acc[nt][0] + bb.x), ww.x, pm[0]);
                pm[0] = fmaf(tanh_fast(acc[nt][1] + bb.y), ww.y, pm[0]);
                pm[1] = fmaf(tanh_fast(acc[nt][2] + bb.x), ww.x, pm[1]);
                pm[1] = fmaf(tanh_fast(acc[nt][3] + bb.y), ww.y, pm[1]);
            }
            #pragma unroll
            for (int h = 0; h < 2; ++h) {
                pm[h] += __shfl_xor_sync(0xffffffffu, pm[h], 1);
                pm[h] += __shfl_xor_sync(0xffffffffu, pm[h], 2);
            }
            if (tq == 0) {
                red[wid][g]     = pm[0];
                red[wid][g + 8] = pm[1];
            }
            __syncthreads();
            if (t < MTILE) {
                float y = __ldg(&b_out[d]);
                #pragma unroll
                for (int w = 0; w < 16; ++w) y += red[w][t];
                const int pidx = blk * MTILE + t;
                if (pidx < T_TAB) g_table[d][pidx] = y;
                else              g_ymm[d][pidx - T_TAB] = y;  // 0: x=-1, 1: x=+1
            }
        }
    }
}

// ---------------------------------------------------------------------------
// Interp: Catmull-Rom through a SMEM-resident table + min-max normalization.
// 512 blocks x 2048 elems (one net each), 8 elems/thread — the shape that
// measured fastest (R8, ~4.5us); 16-elem/256-block measured 7.5us @19% occ.
// ---------------------------------------------------------------------------
__global__ __launch_bounds__(256) void interp_kernel(
    const float* __restrict__ x, float* __restrict__ out)
{
    __shared__ float stab[T_TAB];

    const int t  = threadIdx.x;
    const int d  = blockIdx.x >> 5;          // 32 blocks per net
    const int i8 = blockIdx.x * 256 + t;     // unit of 8 elems (2 float4)

    if (t < T_TAB) stab[t] = g_table[d][t];
    const float ymin = g_ymm[d][0];
    const float s    = 2.0f / (g_ymm[d][1] - ymin);
    __syncthreads();

    const float4 xa = reinterpret_cast<const float4*>(x)[2 * i8];
    const float4 xb = reinterpret_cast<const float4*>(x)[2 * i8 + 1];
    const float xin[8] = {xa.x, xa.y, xa.z, xa.w, xb.x, xb.y, xb.z, xb.w};
    float r[8];
    #pragma unroll
    for (int c = 0; c < 8; ++c) {
        float u = (xin[c] - XMN) * INV_DX;
        u = fminf(fmaxf(u, 0.0f), 141.0f);
        int i = (int)floorf(u);
        i = min(max(i, 1), T_TAB - 3);
        const float tt = u - (float)i;
        const float p0 = stab[i - 1];
        const float p1 = stab[i];
        const float p2 = stab[i + 1];
        const float p3 = stab[i + 2];
        const float y = p1 + 0.5f * tt * ((p2 - p0)
                        + tt * ((2.0f * p0 - 5.0f * p1 + 4.0f * p2 - p3)
                        + tt * (3.0f * (p1 - p2) + p3 - p0)));
        r[c] = fmaf(y - ymin, s, -1.0f);
    }
    reinterpret_cast<float4*>(out)[2 * i8]     = make_float4(r[0], r[1], r[2], r[3]);
    reinterpret_cast<float4*>(out)[2 * i8 + 1] = make_float4(r[4], r[5], r[6], r[7]);
}

// ---------------------------------------------------------------------------
extern "C" void kernel_launch(void* const* d_in, const int* in_sizes, int n_in,
                              void* d_out, int out_size)
{
    const float* x     = (const float*)d_in[0];
    const float* W_in  = (const float*)d_in[1];
    const float* b_in  = (const float*)d_in[2];
    const float* W_mid = (const float*)d_in[3];
    const float* b_mid = (const float*)d_in[4];
    const float* W_out = (const float*)d_in[5];
    const float* b_out = (const float*)d_in[6];

    prep_kernel<<<MM * DD * 32, 128>>>(W_mid);
    build_kernel<<<DD * BPN, 512>>>(W_in, b_in, b_mid, W_out, b_out);

    const int total8 = DD * NN / 8;
    interp_kernel<<<total8 / 256, 256>>>(x, (float*)d_out);
}